// round 2
// baseline (speedup 1.0000x reference)
#include <cuda_runtime.h>
#include <cstdint>

using u64 = unsigned long long;

// ---------------- f32x2 packed-FMA helpers (Blackwell FFMA2) ----------------
__device__ __forceinline__ u64 pack2(float x, float y) {
    u64 r; asm("mov.b64 %0, {%1, %2};" : "=l"(r) : "f"(x), "f"(y)); return r;
}
__device__ __forceinline__ u64 bcast2(float x) {
    u64 r; asm("mov.b64 %0, {%1, %1};" : "=l"(r) : "f"(x)); return r;
}
__device__ __forceinline__ void ffma2(u64& acc, u64 a, u64 b) {
    asm("fma.rn.f32x2 %0, %1, %2, %0;" : "+l"(acc) : "l"(a), "l"(b));
}
__device__ __forceinline__ float2 unpack2(u64 v) {
    float2 f; asm("mov.b64 {%0, %1}, %2;" : "=f"(f.x), "=f"(f.y) : "l"(v)); return f;
}

// ---------------- scratch (static __device__ arrays; no allocations) ----------------
__device__ float g_pool1[512*16*12*36*3];
__device__ float g_pool2[512*32*6*18*3];
__device__ float g_flat [512*64*81];     // (B, D,H,W,C)
__device__ float g_mean [512*64];

// ---------------- fused conv3d(3x3x3,pad1) + relu + maxpool(2,2,1), FFMA2 ----------------
// One thread: output (b, oc0..oc0+NOC-1, dp, hp, w=0..2). Accumulators packed
// pairwise over the hh pool index; input rows packed as sliding hi-pairs.
template<int IC, int DIN, int HIN, int OCT, int NOC, int ZDIM, bool FLAT>
__global__ __launch_bounds__(432, 1)
void convpool_kernel(const float* __restrict__ in,
                     const float* __restrict__ wgt,
                     const float* __restrict__ bias,
                     float* __restrict__ out)
{
    constexpr int DOUT = DIN/2, HOUT = HIN/2;
    constexpr int OCB  = NOC * ZDIM;          // oc covered per block
    constexpr int THREADS = 432;
    __shared__ float wsm[2 * OCB * 27];

    const int hp  = threadIdx.x;
    const int dp  = threadIdx.y;
    const int zt  = threadIdx.z;
    const int oc0 = (blockIdx.y * ZDIM + zt) * NOC;
    const int b   = blockIdx.x;
    const int t   = threadIdx.x + blockDim.x * (threadIdx.y + blockDim.y * threadIdx.z);
    const int ocb_base = blockIdx.y * OCB;

    u64 accP[NOC][2][3];
    #pragma unroll
    for (int o = 0; o < NOC; o++)
        #pragma unroll
        for (int dd = 0; dd < 2; dd++)
            #pragma unroll
            for (int w = 0; w < 3; w++) accP[o][dd][w] = 0ull;

    const float* inb = in + (size_t)b * IC * DIN * HIN * 3;

    // cooperative per-ic weight staging (double buffered)
    auto stage = [&](int ic, int buf) {
        for (int i = t; i < OCB * 27; i += THREADS) {
            int o = i / 27, k = i % 27;
            wsm[buf * OCB * 27 + i] = __ldg(wgt + ((size_t)(ocb_base + o) * IC + ic) * 27 + k);
        }
    };

    stage(0, 0);
    __syncthreads();

    #pragma unroll 1
    for (int ic = 0; ic < IC; ++ic) {
        if (ic + 1 < IC) stage(ic + 1, (ic + 1) & 1);

        const float* inc = inb + (size_t)ic * (DIN * HIN * 3);

        // rolling 2-row window of hi-pair-packed input rows
        u64 pph[2][3][3];
        auto loadrow = [&](int di, u64 (&dst)[3][3]) {
            float pv[4][3];
            int d = 2*dp - 1 + di;
            bool okd = (unsigned)d < (unsigned)DIN;
            #pragma unroll
            for (int hi = 0; hi < 4; ++hi) {
                int h = 2*hp - 1 + hi;
                bool ok = okd && ((unsigned)h < (unsigned)HIN);
                const float* rp = inc + ((size_t)d * HIN + h) * 3;
                pv[hi][0] = ok ? __ldg(rp + 0) : 0.f;
                pv[hi][1] = ok ? __ldg(rp + 1) : 0.f;
                pv[hi][2] = ok ? __ldg(rp + 2) : 0.f;
            }
            #pragma unroll
            for (int j = 0; j < 3; j++)
                #pragma unroll
                for (int w = 0; w < 3; w++)
                    dst[j][w] = pack2(pv[j][w], pv[j+1][w]);
        };

        loadrow(0, pph[0]);
        loadrow(1, pph[1]);

        const float* wrow = wsm + (ic & 1) * OCB * 27 + (zt * NOC) * 27;

        #pragma unroll
        for (int kd = 0; kd < 3; kd++) {
            #pragma unroll
            for (int o = 0; o < NOC; o++) {
                #pragma unroll
                for (int kh = 0; kh < 3; kh++)
                #pragma unroll
                for (int kw = 0; kw < 3; kw++) {
                    u64 wb = bcast2(wrow[o * 27 + (kd*3 + kh)*3 + kw]);
                    #pragma unroll
                    for (int w = 0; w < 3; w++) {
                        int iw = w + kw - 1;
                        if (iw >= 0 && iw < 3) {
                            ffma2(accP[o][0][w], wb, pph[ kd      & 1][kh][iw]);
                            ffma2(accP[o][1][w], wb, pph[(kd + 1) & 1][kh][iw]);
                        }
                    }
                }
            }
            if (kd < 2) loadrow(kd + 2, pph[kd & 1]);
        }
        __syncthreads();
    }

    #pragma unroll
    for (int o = 0; o < NOC; o++) {
        float bv = __ldg(bias + oc0 + o);
        #pragma unroll
        for (int w = 0; w < 3; w++) {
            float2 v0 = unpack2(accP[o][0][w]);   // (dd=0,hh=0), (dd=0,hh=1)
            float2 v1 = unpack2(accP[o][1][w]);   // (dd=1,hh=0), (dd=1,hh=1)
            float v = fmaxf(fmaxf(v0.x, v0.y), fmaxf(v1.x, v1.y));
            v = fmaxf(v + bv, 0.f);
            if (FLAT) {
                out[(size_t)b * (DOUT*HOUT*3*OCT) + (((dp*HOUT) + hp)*3 + w) * OCT + (oc0 + o)] = v;
            } else {
                out[(((size_t)b * OCT + oc0 + o) * DOUT + dp) * (HOUT*3) + hp*3 + w] = v;
            }
        }
    }
}

// ---------------- mean over the 81 spatial positions ----------------
__global__ void mean_kernel()
{
    int b = blockIdx.x, c = threadIdx.x;
    const float* f = g_flat + (size_t)b * 5184 + c;
    float s = 0.f;
    #pragma unroll
    for (int p = 0; p < 81; p++) s += f[p * 64];
    g_mean[b * 64 + c] = s * (1.f / 81.f);
}

// ---------------- smem-tiled matvec with FFMA2: out[n=t][r] += W[n][k]*X[k][r] ----------------
// W: global row-major [256][K].  Xsh: smem [K][4].  Wsh: staging [256][KT+4]. 256 threads.
template<int K, int KT>
__device__ __forceinline__ void matvec2(const float* __restrict__ W,
                                        const float* __restrict__ Xsh,
                                        float* __restrict__ Wsh,
                                        u64& a01, u64& a23, int t)
{
    constexpr int RS = KT + 4;
    constexpr int QP = KT / 4;
    for (int kt = 0; kt < K; kt += KT) {
        __syncthreads();
        #pragma unroll
        for (int i = 0; i < QP; i++) {
            int idx = t + i * 256;
            int n   = idx / QP;
            int kq  = idx % QP;
            *(float4*)(Wsh + n * RS + kq * 4) =
                *(const float4*)(W + (size_t)n * K + kt + kq * 4);
        }
        __syncthreads();
        #pragma unroll
        for (int kk = 0; kk < KT; kk += 4) {
            float4 wv = *(const float4*)(Wsh + t * RS + kk);
            const ulonglong2* xp = (const ulonglong2*)(Xsh + (kt + kk) * 4);
            ulonglong2 x0 = xp[0], x1 = xp[1], x2 = xp[2], x3 = xp[3];
            u64 bb;
            bb = bcast2(wv.x); ffma2(a01, bb, x0.x); ffma2(a23, bb, x0.y);
            bb = bcast2(wv.y); ffma2(a01, bb, x1.x); ffma2(a23, bb, x1.y);
            bb = bcast2(wv.z); ffma2(a01, bb, x2.x); ffma2(a23, bb, x2.y);
            bb = bcast2(wv.w); ffma2(a01, bb, x3.x); ffma2(a23, bb, x3.y);
        }
    }
}

// ---------------- RNN decoder: 128 blocks x 4 batch rows ----------------
__global__ __launch_bounds__(256, 1)
void rnn_kernel(const float* __restrict__ whh1, const float* __restrict__ wih2,
                const float* __restrict__ whh2,
                const float* __restrict__ w_init_h,  const float* __restrict__ b_init_h,
                const float* __restrict__ w_init_h2, const float* __restrict__ b_init_h2,
                const float* __restrict__ wih1, const float* __restrict__ bih1,
                const float* __restrict__ bhh1,
                const float* __restrict__ bih2, const float* __restrict__ bhh2,
                const float* __restrict__ w_fc, const float* __restrict__ b_fc,
                float* __restrict__ preds)
{
    extern __shared__ float sm[];
    float* me   = sm;            //  64*4
    float* hS   = sm + 256;      // 256*4
    float* h2S  = sm + 1280;
    float* ihcS = sm + 2304;
    float* hnS  = sm + 3328;
    float* Wsh  = sm + 4352;     // 256*36

    const int t  = threadIdx.x;
    const int r0 = blockIdx.x * 4;

    { int r = t & 3, k = t >> 2;
      me[k*4 + r] = g_mean[(size_t)(r0 + r) * 64 + k]; }

    u64 a01 = 0ull, a23 = 0ull;
    matvec2<64,32>(w_init_h, me, Wsh, a01, a23, t);
    u64 c01 = 0ull, c23 = 0ull;
    matvec2<64,32>(wih1, me, Wsh, c01, c23, t);
    {
        float bh = __ldg(b_init_h + t);
        float bi = __ldg(bih1 + t) + __ldg(bhh1 + t);
        float2 aL = unpack2(a01), aH = unpack2(a23);
        float2 cL = unpack2(c01), cH = unpack2(c23);
        hS[t*4+0] = aL.x + bh; hS[t*4+1] = aL.y + bh;
        hS[t*4+2] = aH.x + bh; hS[t*4+3] = aH.y + bh;
        ihcS[t*4+0] = cL.x + bi; ihcS[t*4+1] = cL.y + bi;
        ihcS[t*4+2] = cH.x + bi; ihcS[t*4+3] = cH.y + bi;
    }
    u64 g01 = 0ull, g23 = 0ull;
    matvec2<256,32>(w_init_h2, hS, Wsh, g01, g23, t);
    {
        float b2 = __ldg(b_init_h2 + t);
        float2 gL = unpack2(g01), gH = unpack2(g23);
        h2S[t*4+0] = gL.x + b2; h2S[t*4+1] = gL.y + b2;
        h2S[t*4+2] = gH.x + b2; h2S[t*4+3] = gH.y + b2;
    }
    const float bi2 = __ldg(bih2 + t) + __ldg(bhh2 + t);
    const float bfc = __ldg(b_fc);

    for (int step = 0; step < 23; ++step) {
        u64 h01 = 0ull, h23 = 0ull;
        matvec2<256,32>(whh1, hS, Wsh, h01, h23, t);   // internal syncs order prior smem writes
        {
            float2 hL = unpack2(h01), hH = unpack2(h23);
            hnS[t*4+0] = tanhf(ihcS[t*4+0] + hL.x);
            hnS[t*4+1] = tanhf(ihcS[t*4+1] + hL.y);
            hnS[t*4+2] = tanhf(ihcS[t*4+2] + hH.x);
            hnS[t*4+3] = tanhf(ihcS[t*4+3] + hH.y);
        }
        u64 u01 = 0ull, u23 = 0ull;
        matvec2<256,32>(wih2, hnS, Wsh, u01, u23, t);
        u64 v01 = 0ull, v23 = 0ull;
        matvec2<256,32>(whh2, h2S, Wsh, v01, v23, t);
        __syncthreads();
        {
            float2 uL = unpack2(u01), uH = unpack2(u23);
            float2 vL = unpack2(v01), vH = unpack2(v23);
            h2S[t*4+0] = tanhf(uL.x + vL.x + bi2);
            h2S[t*4+1] = tanhf(uL.y + vL.y + bi2);
            h2S[t*4+2] = tanhf(uH.x + vH.x + bi2);
            h2S[t*4+3] = tanhf(uH.y + vH.y + bi2);
            hS[t*4+0] = hnS[t*4+0]; hS[t*4+1] = hnS[t*4+1];
            hS[t*4+2] = hnS[t*4+2]; hS[t*4+3] = hnS[t*4+3];
        }
        __syncthreads();
        if (t < 128) {
            int r = t >> 5, lane = t & 31;
            float s = 0.f;
            #pragma unroll
            for (int k = lane; k < 256; k += 32) s += __ldg(w_fc + k) * h2S[k*4 + r];
            #pragma unroll
            for (int off = 16; off; off >>= 1) s += __shfl_down_sync(0xffffffffu, s, off);
            if (lane == 0) preds[(size_t)(r0 + r) * 23 + step] = s + bfc;
        }
    }
}

// ---------------- linear head ----------------
__global__ __launch_bounds__(256, 1)
void head_kernel(const float* __restrict__ w_lin1, const float* __restrict__ b_lin1,
                 const float* __restrict__ w_lin2, const float* __restrict__ b_lin2,
                 float* __restrict__ outc)
{
    extern __shared__ float sm[];
    float* xS  = sm;             // 5184*4
    float* thS = sm + 20736;     // 1024
    float* Wsh = sm + 21760;     // 256*68
    const int t  = threadIdx.x;
    const int r0 = blockIdx.x * 4;

    for (int idx = t; idx < 4 * 5184; idx += 256) {
        int r = idx / 5184, k = idx % 5184;
        xS[k*4 + r] = g_flat[(size_t)(r0 + r) * 5184 + k];
    }

    u64 a01 = 0ull, a23 = 0ull;
    matvec2<5184,64>(w_lin1, xS, Wsh, a01, a23, t);
    float bl = __ldg(b_lin1 + t);
    {
        float2 aL = unpack2(a01), aH = unpack2(a23);
        thS[t*4+0] = tanhf(aL.x + bl); thS[t*4+1] = tanhf(aL.y + bl);
        thS[t*4+2] = tanhf(aH.x + bl); thS[t*4+3] = tanhf(aH.y + bl);
    }
    __syncthreads();

    if (t < 48) {
        int n = t % 12, r = t / 12;
        float s = 0.f;
        #pragma unroll 4
        for (int k = 0; k < 256; k++) s += __ldg(w_lin2 + n*256 + k) * thS[k*4 + r];
        outc[(size_t)(r0 + r) * 12 + n] = s + __ldg(b_lin2 + n);
    }
}

// ---------------- launch ----------------
extern "C" void kernel_launch(void* const* d_in, const int* in_sizes, int n_in,
                              void* d_out, int out_size)
{
    const float* x    = (const float*)d_in[0];
    const float* w1   = (const float*)d_in[1];
    const float* b1   = (const float*)d_in[2];
    const float* w2   = (const float*)d_in[3];
    const float* b2   = (const float*)d_in[4];
    const float* w3   = (const float*)d_in[5];
    const float* b3   = (const float*)d_in[6];
    const float* wih1 = (const float*)d_in[7];
    const float* whh1 = (const float*)d_in[8];
    const float* bih1 = (const float*)d_in[9];
    const float* bhh1 = (const float*)d_in[10];
    const float* wih2 = (const float*)d_in[11];
    const float* whh2 = (const float*)d_in[12];
    const float* bih2 = (const float*)d_in[13];
    const float* bhh2 = (const float*)d_in[14];
    const float* w_init_h  = (const float*)d_in[15];
    const float* b_init_h  = (const float*)d_in[16];
    const float* w_init_h2 = (const float*)d_in[17];
    const float* b_init_h2 = (const float*)d_in[18];
    const float* w_fc  = (const float*)d_in[19];
    const float* b_fc  = (const float*)d_in[20];
    const float* w_lin1 = (const float*)d_in[21];
    const float* b_lin1 = (const float*)d_in[22];
    const float* w_lin2 = (const float*)d_in[23];
    const float* b_lin2 = (const float*)d_in[24];
    float* out = (float*)d_out;

    float *p1, *p2, *pf;
    cudaGetSymbolAddress((void**)&p1, g_pool1);
    cudaGetSymbolAddress((void**)&p2, g_pool2);
    cudaGetSymbolAddress((void**)&pf, g_flat);

    // stage 1: (512,6,24,72,3) -> (512,16,12,36,3)
    convpool_kernel<6, 24, 72, 16, 4, 1, false>
        <<<dim3(512, 4), dim3(36, 12, 1)>>>(x, w1, b1, p1);
    // stage 2: -> (512,32,6,18,3)
    convpool_kernel<16, 12, 36, 32, 4, 4, false>
        <<<dim3(512, 2), dim3(18, 6, 4)>>>(p1, w2, b2, p2);
    // stage 3: -> (512, 3,9,3, 64) flat layout
    convpool_kernel<32, 6, 18, 64, 4, 16, true>
        <<<dim3(512, 1), dim3(9, 3, 16)>>>(p2, w3, b3, pf);

    mean_kernel<<<512, 64>>>();

    cudaFuncSetAttribute(rnn_kernel, cudaFuncAttributeMaxDynamicSharedMemorySize, 54272);
    rnn_kernel<<<128, 256, 54272>>>(whh1, wih2, whh2,
                                    w_init_h, b_init_h, w_init_h2, b_init_h2,
                                    wih1, bih1, bhh1, bih2, bhh2,
                                    w_fc, b_fc, out);

    cudaFuncSetAttribute(head_kernel, cudaFuncAttributeMaxDynamicSharedMemorySize, 156672);
    head_kernel<<<128, 256, 156672>>>(w_lin1, b_lin1, w_lin2, b_lin2,
                                      out + 512 * 23);
}